// round 4
// baseline (speedup 1.0000x reference)
#include <cuda_runtime.h>
#include <cstdint>

// Problem constants (fixed by the dataset)
#define T_TOKENS 2048
#define T_HIDDEN 2048
#define T_INTER  768
#define T_NEXP   16
#define T_TOPK   2
#define T_NPAIRS (T_TOKENS * T_TOPK)   // 4096

#define NTHREADS 256

// -------- device-global scratch (no allocations allowed) --------
__device__ int   g_offs[T_NEXP + 1];
__device__ int   g_tok[T_NPAIRS];
__device__ float g_wt[T_NPAIRS];
__device__ float g_h[(size_t)T_NPAIRS * T_INTER];   // 12.58 MB intermediate activations

// ----------------------------------------------------------------
// Routing: bucket (token, k) pairs by expert. Runtime int32/int64
// detection (odd 32-bit words of little-endian int64 0..15 are 0).
// ----------------------------------------------------------------
__global__ void route_kernel(const int* __restrict__ idx32, const float* __restrict__ w) {
    __shared__ int cnt[T_NEXP];
    __shared__ int base[T_NEXP];
    __shared__ int cur[T_NEXP];
    __shared__ int odd_nonzero;
    int tid = threadIdx.x;
    if (tid < T_NEXP) cnt[tid] = 0;
    if (tid == 0) odd_nonzero = 0;
    __syncthreads();

    for (int j = tid; j < T_NPAIRS; j += NTHREADS) {
        if ((j & 1) && idx32[j] != 0) odd_nonzero = 1;
    }
    __syncthreads();
    bool i64 = (odd_nonzero == 0);

    for (int p = tid; p < T_NPAIRS; p += NTHREADS) {
        int e = i64 ? idx32[2 * p] : idx32[p];
        atomicAdd(&cnt[e], 1);
    }
    __syncthreads();
    if (tid == 0) {
        int s = 0;
        for (int e = 0; e < T_NEXP; e++) {
            base[e] = s; cur[e] = 0; g_offs[e] = s; s += cnt[e];
        }
        g_offs[T_NEXP] = s;
    }
    __syncthreads();
    for (int p = tid; p < T_NPAIRS; p += NTHREADS) {
        int e = i64 ? idx32[2 * p] : idx32[p];
        int slot = base[e] + atomicAdd(&cur[e], 1);
        g_tok[slot] = p >> 1;
        g_wt[slot]  = w[p];
    }
}

__global__ void zero_kernel(float4* __restrict__ out) {
    int i = blockIdx.x * blockDim.x + threadIdx.x;
    out[i] = make_float4(0.f, 0.f, 0.f, 0.f);
}

// ----------------------------------------------------------------
// GEMM1 (fused gate+up+SwiGLU), 128x64 tile, BK=8, double-buffered.
// Each thread: 8 M-rows x 4 N-cols for BOTH gate and up (shared A frag).
//   h[s, n] = silu(x[tok_s] . Wg[e,n,:]) * (x[tok_s] . Wu[e,n,:])
// ----------------------------------------------------------------
#define G1_BM 128
#define G1_BN 64
#define G1_BK 8

__global__ __launch_bounds__(NTHREADS)
void gemm1_kernel(const float* __restrict__ x,
                  const float* __restrict__ Wg,
                  const float* __restrict__ Wu) {
    int e   = blockIdx.z;
    int off = g_offs[e];
    int cnt = g_offs[e + 1] - off;
    int m0  = blockIdx.y * G1_BM;
    if (m0 >= cnt) return;
    int n0  = blockIdx.x * G1_BN;

    __shared__ float As[2][G1_BK][G1_BM];
    __shared__ float Gs[2][G1_BK][G1_BN];
    __shared__ float Us[2][G1_BK][G1_BN];

    int tid = threadIdx.x;
    int tx = tid & 15;            // N: 16 cols of 4
    int ty = tid >> 4;            // M: 16 groups of 8 (4 + 4 split by 64)

    // A load mapping: 128 rows x 8 k; 2 threads/row, float4 each
    int am = tid >> 1;
    int ak = (tid & 1) << 2;
    const float* arow = nullptr;
    if (m0 + am < cnt) arow = x + (size_t)g_tok[off + m0 + am] * T_HIDDEN + ak;

    // B load mapping: threads 0-127 load gate, 128-255 load up
    int bt = tid & 127;
    int bn = bt >> 1;
    int bk = (bt & 1) << 2;
    const float* wsel = (tid < 128) ? Wg : Wu;
    const float* brow = wsel + (size_t)e * T_INTER * T_HIDDEN
                             + (size_t)(n0 + bn) * T_HIDDEN + bk;

    float accg[8][4] = {};
    float accu[8][4] = {};

    float4 pa, pb;
    // prologue: stage 0
    pa = arow ? *(const float4*)(arow) : make_float4(0.f, 0.f, 0.f, 0.f);
    pb = *(const float4*)(brow);
    As[0][ak + 0][am] = pa.x; As[0][ak + 1][am] = pa.y;
    As[0][ak + 2][am] = pa.z; As[0][ak + 3][am] = pa.w;
    if (tid < 128) {
        Gs[0][bk + 0][bn] = pb.x; Gs[0][bk + 1][bn] = pb.y;
        Gs[0][bk + 2][bn] = pb.z; Gs[0][bk + 3][bn] = pb.w;
    } else {
        Us[0][bk + 0][bn] = pb.x; Us[0][bk + 1][bn] = pb.y;
        Us[0][bk + 2][bn] = pb.z; Us[0][bk + 3][bn] = pb.w;
    }
    __syncthreads();

    int buf = 0;
    for (int k0 = 0; k0 < T_HIDDEN; k0 += G1_BK) {
        int nxt = k0 + G1_BK;
        bool more = nxt < T_HIDDEN;
        if (more) {
            pa = arow ? *(const float4*)(arow + nxt) : make_float4(0.f, 0.f, 0.f, 0.f);
            pb = *(const float4*)(brow + nxt);
        }
        #pragma unroll
        for (int kk = 0; kk < G1_BK; kk++) {
            float4 a0 = *(const float4*)&As[buf][kk][ty << 2];
            float4 a1 = *(const float4*)&As[buf][kk][(ty << 2) + 64];
            float4 g4 = *(const float4*)&Gs[buf][kk][tx << 2];
            float4 u4 = *(const float4*)&Us[buf][kk][tx << 2];
            float a[8] = {a0.x, a0.y, a0.z, a0.w, a1.x, a1.y, a1.z, a1.w};
            float g[4] = {g4.x, g4.y, g4.z, g4.w};
            float u[4] = {u4.x, u4.y, u4.z, u4.w};
            #pragma unroll
            for (int i = 0; i < 8; i++)
                #pragma unroll
                for (int j = 0; j < 4; j++) {
                    accg[i][j] += a[i] * g[j];
                    accu[i][j] += a[i] * u[j];
                }
        }
        if (more) {
            int nb = buf ^ 1;
            As[nb][ak + 0][am] = pa.x; As[nb][ak + 1][am] = pa.y;
            As[nb][ak + 2][am] = pa.z; As[nb][ak + 3][am] = pa.w;
            if (tid < 128) {
                Gs[nb][bk + 0][bn] = pb.x; Gs[nb][bk + 1][bn] = pb.y;
                Gs[nb][bk + 2][bn] = pb.z; Gs[nb][bk + 3][bn] = pb.w;
            } else {
                Us[nb][bk + 0][bn] = pb.x; Us[nb][bk + 1][bn] = pb.y;
                Us[nb][bk + 2][bn] = pb.z; Us[nb][bk + 3][bn] = pb.w;
            }
            __syncthreads();
            buf = nb;
        }
    }

    #pragma unroll
    for (int i = 0; i < 8; i++) {
        int r = m0 + (ty << 2) + ((i < 4) ? i : (60 + i));  // rows ty*4+i / ty*4+64+(i-4)
        if (r < cnt) {
            float* hrow = g_h + (size_t)(off + r) * T_INTER + n0 + (tx << 2);
            float4 o;
            float gg, ss;
            gg = accg[i][0]; ss = gg / (1.f + __expf(-gg)); o.x = ss * accu[i][0];
            gg = accg[i][1]; ss = gg / (1.f + __expf(-gg)); o.y = ss * accu[i][1];
            gg = accg[i][2]; ss = gg / (1.f + __expf(-gg)); o.z = ss * accu[i][2];
            gg = accg[i][3]; ss = gg / (1.f + __expf(-gg)); o.w = ss * accu[i][3];
            *(float4*)hrow = o;
        }
    }
}

// ----------------------------------------------------------------
// GEMM2 (down proj + weighted scatter-add), 128x128 tile, BK=8,
// double-buffered, 8x8 per-thread register tile.
//   out[tok_s, n] += w_s * (h[s,:] . Wd[e,n,:])
// ----------------------------------------------------------------
#define G2_BM 128
#define G2_BN 128
#define G2_BK 8

__global__ __launch_bounds__(NTHREADS)
void gemm2_kernel(const float* __restrict__ Wd, float* __restrict__ out) {
    int e   = blockIdx.z;
    int off = g_offs[e];
    int cnt = g_offs[e + 1] - off;
    int m0  = blockIdx.y * G2_BM;
    if (m0 >= cnt) return;
    int n0  = blockIdx.x * G2_BN;

    __shared__ float As[2][G2_BK][G2_BM];
    __shared__ float Bs[2][G2_BK][G2_BN];

    int tid = threadIdx.x;
    int tx = tid & 15;
    int ty = tid >> 4;

    int am = tid >> 1;
    int ak = (tid & 1) << 2;
    const float* arow = nullptr;
    if (m0 + am < cnt) arow = g_h + (size_t)(off + m0 + am) * T_INTER + ak;

    const float* brow = Wd + (size_t)e * T_HIDDEN * T_INTER
                           + (size_t)(n0 + am) * T_INTER + ak;

    float acc[8][8] = {};

    float4 pa, pb;
    pa = arow ? *(const float4*)(arow) : make_float4(0.f, 0.f, 0.f, 0.f);
    pb = *(const float4*)(brow);
    As[0][ak + 0][am] = pa.x; As[0][ak + 1][am] = pa.y;
    As[0][ak + 2][am] = pa.z; As[0][ak + 3][am] = pa.w;
    Bs[0][ak + 0][am] = pb.x; Bs[0][ak + 1][am] = pb.y;
    Bs[0][ak + 2][am] = pb.z; Bs[0][ak + 3][am] = pb.w;
    __syncthreads();

    int buf = 0;
    for (int k0 = 0; k0 < T_INTER; k0 += G2_BK) {
        int nxt = k0 + G2_BK;
        bool more = nxt < T_INTER;
        if (more) {
            pa = arow ? *(const float4*)(arow + nxt) : make_float4(0.f, 0.f, 0.f, 0.f);
            pb = *(const float4*)(brow + nxt);
        }
        #pragma unroll
        for (int kk = 0; kk < G2_BK; kk++) {
            float4 a0 = *(const float4*)&As[buf][kk][ty << 2];
            float4 a1 = *(const float4*)&As[buf][kk][(ty << 2) + 64];
            float4 b0 = *(const float4*)&Bs[buf][kk][tx << 2];
            float4 b1 = *(const float4*)&Bs[buf][kk][(tx << 2) + 64];
            float a[8] = {a0.x, a0.y, a0.z, a0.w, a1.x, a1.y, a1.z, a1.w};
            float b[8] = {b0.x, b0.y, b0.z, b0.w, b1.x, b1.y, b1.z, b1.w};
            #pragma unroll
            for (int i = 0; i < 8; i++)
                #pragma unroll
                for (int j = 0; j < 8; j++)
                    acc[i][j] += a[i] * b[j];
        }
        if (more) {
            int nb = buf ^ 1;
            As[nb][ak + 0][am] = pa.x; As[nb][ak + 1][am] = pa.y;
            As[nb][ak + 2][am] = pa.z; As[nb][ak + 3][am] = pa.w;
            Bs[nb][ak + 0][am] = pb.x; Bs[nb][ak + 1][am] = pb.y;
            Bs[nb][ak + 2][am] = pb.z; Bs[nb][ak + 3][am] = pb.w;
            __syncthreads();
            buf = nb;
        }
    }

    #pragma unroll
    for (int i = 0; i < 8; i++) {
        int r = m0 + (ty << 2) + ((i < 4) ? i : (60 + i));
        if (r < cnt) {
            int   tok = g_tok[off + r];
            float wgt = g_wt[off + r];
            float* orow = out + (size_t)tok * T_HIDDEN + n0;
            #pragma unroll
            for (int j = 0; j < 8; j++) {
                int c = (tx << 2) + ((j < 4) ? j : (60 + j));
                atomicAdd(&orow[c], wgt * acc[i][j]);
            }
        }
    }
}

// ----------------------------------------------------------------
extern "C" void kernel_launch(void* const* d_in, const int* in_sizes, int n_in,
                              void* d_out, int out_size) {
    const float* x   = (const float*)d_in[0];   // [2048, 2048] fp32
    const int*   idx = (const int*)d_in[1];     // [2048, 2] int32/int64 (runtime-detected)
    const float* w   = (const float*)d_in[2];   // [2048, 2] fp32
    const float* Wg  = (const float*)d_in[3];   // [16, 768, 2048] fp32
    const float* Wu  = (const float*)d_in[4];   // [16, 768, 2048] fp32
    const float* Wd  = (const float*)d_in[5];   // [16, 2048, 768] fp32
    float* out = (float*)d_out;                 // [2048, 2048] fp32

    route_kernel<<<1, NTHREADS>>>(idx, w);
    zero_kernel<<<(T_TOKENS * T_HIDDEN / 4) / NTHREADS, NTHREADS>>>((float4*)out);
    gemm1_kernel<<<dim3(T_INTER / G1_BN, T_NPAIRS / G1_BM, T_NEXP), NTHREADS>>>(x, Wg, Wu);
    gemm2_kernel<<<dim3(T_HIDDEN / G2_BN, T_NPAIRS / G2_BM, T_NEXP), NTHREADS>>>(Wd, out);
}

// round 7
// speedup vs baseline: 2.0860x; 2.0860x over previous
#include <cuda_runtime.h>
#include <cuda_bf16.h>
#include <cstdint>

#define T_TOKENS 2048
#define T_HIDDEN 2048
#define T_INTER  768
#define T_NEXP   16
#define T_NPAIRS 4096
#define NTH 256
#define SA 40          // smem row stride in bf16 elements (80B: conflict-free ldmatrix)

// -------- device-global scratch (no allocations allowed) --------
__device__ int   g_offs[T_NEXP + 1];
__device__ int   g_tok[T_NPAIRS];
__device__ float g_wt[T_NPAIRS];

#define NW ((size_t)T_NEXP * T_INTER * T_HIDDEN)     // 25,165,824 per weight tensor
__device__ alignas(16) __nv_bfloat16 s_x_hi[(size_t)T_TOKENS * T_HIDDEN];
__device__ alignas(16) __nv_bfloat16 s_x_lo[(size_t)T_TOKENS * T_HIDDEN];
__device__ alignas(16) __nv_bfloat16 s_wg_hi[NW];
__device__ alignas(16) __nv_bfloat16 s_wg_lo[NW];
__device__ alignas(16) __nv_bfloat16 s_wu_hi[NW];
__device__ alignas(16) __nv_bfloat16 s_wu_lo[NW];
__device__ alignas(16) __nv_bfloat16 s_wd_hi[NW];
__device__ alignas(16) __nv_bfloat16 s_wd_lo[NW];
__device__ alignas(16) __nv_bfloat16 s_h_hi[(size_t)T_NPAIRS * T_INTER];
__device__ alignas(16) __nv_bfloat16 s_h_lo[(size_t)T_NPAIRS * T_INTER];

// ================= helpers =================
__device__ __forceinline__ uint32_t smem_u32(const void* p) {
    uint32_t a;
    asm("{ .reg .u64 t; cvta.to.shared.u64 t, %1; cvt.u32.u64 %0, t; }" : "=r"(a) : "l"(p));
    return a;
}
// fp32 pair -> bf16x2 hi word + bf16x2 lo-residual word (low half = first arg)
__device__ __forceinline__ void pack2(float a, float b, uint32_t& h, uint32_t& l) {
    asm("cvt.rn.bf16x2.f32 %0, %1, %2;" : "=r"(h) : "f"(b), "f"(a));
    float ha = __uint_as_float(h << 16);
    float hb = __uint_as_float(h & 0xffff0000u);
    float la = a - ha;
    float lb = b - hb;
    asm("cvt.rn.bf16x2.f32 %0, %1, %2;" : "=r"(l) : "f"(lb), "f"(la));
}
__device__ __forceinline__ void ldsm4(uint32_t* r, uint32_t addr) {
    asm volatile("ldmatrix.sync.aligned.m8n8.x4.shared.b16 {%0,%1,%2,%3}, [%4];"
                 : "=r"(r[0]), "=r"(r[1]), "=r"(r[2]), "=r"(r[3]) : "r"(addr));
}
__device__ __forceinline__ void mma_bf16(float* d, const uint32_t* a, const uint32_t* b) {
    asm volatile(
        "mma.sync.aligned.m16n8k16.row.col.f32.bf16.bf16.f32 "
        "{%0,%1,%2,%3},{%4,%5,%6,%7},{%8,%9},{%0,%1,%2,%3};"
        : "+f"(d[0]), "+f"(d[1]), "+f"(d[2]), "+f"(d[3])
        : "r"(a[0]), "r"(a[1]), "r"(a[2]), "r"(a[3]), "r"(b[0]), "r"(b[1]));
}

// ================= routing =================
__global__ void route_kernel(const int* __restrict__ idx32, const float* __restrict__ w) {
    __shared__ int cnt[T_NEXP];
    __shared__ int base[T_NEXP];
    __shared__ int cur[T_NEXP];
    __shared__ int odd_nonzero;
    int tid = threadIdx.x;
    if (tid < T_NEXP) cnt[tid] = 0;
    if (tid == 0) odd_nonzero = 0;
    __syncthreads();
    for (int j = tid; j < T_NPAIRS; j += NTH)
        if ((j & 1) && idx32[j] != 0) odd_nonzero = 1;
    __syncthreads();
    bool i64 = (odd_nonzero == 0);
    for (int p = tid; p < T_NPAIRS; p += NTH) {
        int e = i64 ? idx32[2 * p] : idx32[p];
        atomicAdd(&cnt[e], 1);
    }
    __syncthreads();
    if (tid == 0) {
        int s = 0;
        for (int e = 0; e < T_NEXP; e++) { base[e] = s; cur[e] = 0; g_offs[e] = s; s += cnt[e]; }
        g_offs[T_NEXP] = s;
    }
    __syncthreads();
    for (int p = tid; p < T_NPAIRS; p += NTH) {
        int e = i64 ? idx32[2 * p] : idx32[p];
        int slot = base[e] + atomicAdd(&cur[e], 1);
        g_tok[slot] = p >> 1;
        g_wt[slot]  = w[p];
    }
}

__global__ void zero_kernel(float4* __restrict__ out) {
    out[blockIdx.x * blockDim.x + threadIdx.x] = make_float4(0.f, 0.f, 0.f, 0.f);
}

// ============ fp32 -> bf16 hi/lo conversion (one pass per tensor) ============
__global__ void conv_kernel(const float4* __restrict__ src, int n4, int which) {
    uint2* hi; uint2* lo;
    switch (which) {
        case 0:  hi = (uint2*)s_wg_hi; lo = (uint2*)s_wg_lo; break;
        case 1:  hi = (uint2*)s_wu_hi; lo = (uint2*)s_wu_lo; break;
        case 2:  hi = (uint2*)s_wd_hi; lo = (uint2*)s_wd_lo; break;
        default: hi = (uint2*)s_x_hi;  lo = (uint2*)s_x_lo;  break;
    }
    int i = blockIdx.x * NTH + threadIdx.x;
    if (i >= n4) return;
    float4 v = src[i];
    uint32_t h0, l0, h1, l1;
    pack2(v.x, v.y, h0, l0);
    pack2(v.z, v.w, h1, l1);
    hi[i] = make_uint2(h0, h1);
    lo[i] = make_uint2(l0, l1);
}

// ================= GEMM1: fused gate+up+SwiGLU (mma.sync bf16 hi/lo) =========
// CTA tile M=128 (pairs) x N=64 (inter), K=2048, chunk 32. 8 warps 4x2,
// warp tile 32x32 per matrix (gate & up share A fragments).
// smem (bf16 el): Ah 0, Al 5120, Gh 10240, Gl 12800, Uh 15360, Ul 17920.
__global__ __launch_bounds__(NTH, 2)
void gemm1_mma() {
    int e   = blockIdx.z;
    int off = g_offs[e], cnt = g_offs[e + 1] - off;
    int m0  = blockIdx.y * 128;
    if (m0 >= cnt) return;
    int n0  = blockIdx.x * 64;

    __shared__ alignas(128) __nv_bfloat16 sm[20480];
    uint32_t sb = smem_u32(sm);
    int tid = threadIdx.x, wid = tid >> 5, l = tid & 31;

    size_t a_src[2]; uint32_t a_dst[2];
    #pragma unroll
    for (int i = 0; i < 2; i++) {
        int q = tid + NTH * i;
        int row = q >> 2, qc = q & 3;
        int r = m0 + row;
        int tok = g_tok[off + (r < cnt ? r : 0)];
        a_src[i] = (size_t)tok * T_HIDDEN + 8 * qc;
        a_dst[i] = row * SA + 8 * qc;
    }
    size_t b_src = (size_t)e * T_INTER * T_HIDDEN
                 + (size_t)(n0 + (tid >> 2)) * T_HIDDEN + 8 * (tid & 3);
    uint32_t b_dst = (tid >> 2) * SA + 8 * (tid & 3);

    int wm = (wid >> 1) * 32, wn = (wid & 1) * 32;
    uint32_t aL = ((l & 7) + ((l >> 3) & 1) * 8) * SA + ((l >> 4) & 1) * 8;
    uint32_t bL = ((l & 7) + ((l >> 4) & 1) * 8) * SA + ((l >> 3) & 1) * 8;

    float accg[2][4][4] = {}, accu[2][4][4] = {};

    for (int c = 0; c < T_HIDDEN / 32; c++) {
        int kc = c * 32;
        __syncthreads();
        #pragma unroll
        for (int i = 0; i < 2; i++) {
            *(uint4*)&sm[a_dst[i]]        = *(const uint4*)&s_x_hi[a_src[i] + kc];
            *(uint4*)&sm[5120 + a_dst[i]] = *(const uint4*)&s_x_lo[a_src[i] + kc];
        }
        *(uint4*)&sm[10240 + b_dst] = *(const uint4*)&s_wg_hi[b_src + kc];
        *(uint4*)&sm[12800 + b_dst] = *(const uint4*)&s_wg_lo[b_src + kc];
        *(uint4*)&sm[15360 + b_dst] = *(const uint4*)&s_wu_hi[b_src + kc];
        *(uint4*)&sm[17920 + b_dst] = *(const uint4*)&s_wu_lo[b_src + kc];
        __syncthreads();

        #pragma unroll
        for (int ks = 0; ks < 2; ks++) {
            uint32_t kh = ks * 16;
            uint32_t ah[2][4], al[2][4], gh[4][2], gl[4][2], uh[4][2], ul[4][2];
            #pragma unroll
            for (int mi = 0; mi < 2; mi++) {
                uint32_t base = aL + (wm + 16 * mi) * SA + kh;
                ldsm4(ah[mi], sb + 2 * base);
                ldsm4(al[mi], sb + 2 * (5120 + base));
            }
            #pragma unroll
            for (int ng = 0; ng < 2; ng++) {
                uint32_t base = bL + (wn + 16 * ng) * SA + kh;
                uint32_t t[4];
                ldsm4(t, sb + 2 * (10240 + base));
                gh[2*ng][0] = t[0]; gh[2*ng][1] = t[1]; gh[2*ng+1][0] = t[2]; gh[2*ng+1][1] = t[3];
                ldsm4(t, sb + 2 * (12800 + base));
                gl[2*ng][0] = t[0]; gl[2*ng][1] = t[1]; gl[2*ng+1][0] = t[2]; gl[2*ng+1][1] = t[3];
                ldsm4(t, sb + 2 * (15360 + base));
                uh[2*ng][0] = t[0]; uh[2*ng][1] = t[1]; uh[2*ng+1][0] = t[2]; uh[2*ng+1][1] = t[3];
                ldsm4(t, sb + 2 * (17920 + base));
                ul[2*ng][0] = t[0]; ul[2*ng][1] = t[1]; ul[2*ng+1][0] = t[2]; ul[2*ng+1][1] = t[3];
            }
            #pragma unroll
            for (int mi = 0; mi < 2; mi++)
                #pragma unroll
                for (int ni = 0; ni < 4; ni++) mma_bf16(accg[mi][ni], ah[mi], gh[ni]);
            #pragma unroll
            for (int mi = 0; mi < 2; mi++)
                #pragma unroll
                for (int ni = 0; ni < 4; ni++) mma_bf16(accu[mi][ni], ah[mi], uh[ni]);
            #pragma unroll
            for (int mi = 0; mi < 2; mi++)
                #pragma unroll
                for (int ni = 0; ni < 4; ni++) mma_bf16(accg[mi][ni], ah[mi], gl[ni]);
            #pragma unroll
            for (int mi = 0; mi < 2; mi++)
                #pragma unroll
                for (int ni = 0; ni < 4; ni++) mma_bf16(accu[mi][ni], ah[mi], ul[ni]);
            #pragma unroll
            for (int mi = 0; mi < 2; mi++)
                #pragma unroll
                for (int ni = 0; ni < 4; ni++) mma_bf16(accg[mi][ni], al[mi], gh[ni]);
            #pragma unroll
            for (int mi = 0; mi < 2; mi++)
                #pragma unroll
                for (int ni = 0; ni < 4; ni++) mma_bf16(accu[mi][ni], al[mi], uh[ni]);
        }
    }

    // epilogue: silu(g)*u -> bf16 hi/lo planes of h
    int lr = l >> 2, lc = 2 * (l & 3);
    #pragma unroll
    for (int mi = 0; mi < 2; mi++)
        #pragma unroll
        for (int ni = 0; ni < 4; ni++) {
            int col = n0 + wn + ni * 8 + lc;
            #pragma unroll
            for (int h2 = 0; h2 < 2; h2++) {
                int r = m0 + wm + 16 * mi + lr + 8 * h2;
                if (r < cnt) {
                    float g0 = accg[mi][ni][2*h2],     g1 = accg[mi][ni][2*h2+1];
                    float u0 = accu[mi][ni][2*h2],     u1 = accu[mi][ni][2*h2+1];
                    float f0 = g0 / (1.f + __expf(-g0)) * u0;
                    float f1 = g1 / (1.f + __expf(-g1)) * u1;
                    uint32_t hw, lw;
                    pack2(f0, f1, hw, lw);
                    size_t o = (size_t)(off + r) * T_INTER + col;
                    *(uint32_t*)&s_h_hi[o] = hw;
                    *(uint32_t*)&s_h_lo[o] = lw;
                }
            }
        }
}

// ================= GEMM2: down proj + weighted scatter-add ===================
// CTA tile M=128 x N=128, K=768, chunk 32. 8 warps 4x2, warp tile 32x64.
// smem (bf16 el): Ah 0, Al 5120, Bh 10240, Bl 15360.
__global__ __launch_bounds__(NTH, 2)
void gemm2_mma(float* __restrict__ out) {
    int e   = blockIdx.z;
    int off = g_offs[e], cnt = g_offs[e + 1] - off;
    int m0  = blockIdx.y * 128;
    if (m0 >= cnt) return;
    int n0  = blockIdx.x * 128;

    __shared__ alignas(128) __nv_bfloat16 sm[20480];
    uint32_t sb = smem_u32(sm);
    int tid = threadIdx.x, wid = tid >> 5, l = tid & 31;

    size_t a_src[2], b_src[2]; uint32_t ab_dst[2];
    #pragma unroll
    for (int i = 0; i < 2; i++) {
        int q = tid + NTH * i;
        int row = q >> 2, qc = q & 3;
        int sl = off + m0 + row;
        if (sl > T_NPAIRS - 1) sl = T_NPAIRS - 1;
        a_src[i] = (size_t)sl * T_INTER + 8 * qc;
        b_src[i] = (size_t)e * T_HIDDEN * T_INTER + (size_t)(n0 + row) * T_INTER + 8 * qc;
        ab_dst[i] = row * SA + 8 * qc;
    }
    int wm = (wid >> 1) * 32, wn = (wid & 1) * 64;
    uint32_t aL = ((l & 7) + ((l >> 3) & 1) * 8) * SA + ((l >> 4) & 1) * 8;
    uint32_t bL = ((l & 7) + ((l >> 4) & 1) * 8) * SA + ((l >> 3) & 1) * 8;

    float acc[2][8][4] = {};

    for (int c = 0; c < T_INTER / 32; c++) {
        int kc = c * 32;
        __syncthreads();
        #pragma unroll
        for (int i = 0; i < 2; i++) {
            *(uint4*)&sm[ab_dst[i]]         = *(const uint4*)&s_h_hi[a_src[i] + kc];
            *(uint4*)&sm[5120  + ab_dst[i]] = *(const uint4*)&s_h_lo[a_src[i] + kc];
            *(uint4*)&sm[10240 + ab_dst[i]] = *(const uint4*)&s_wd_hi[b_src[i] + kc];
            *(uint4*)&sm[15360 + ab_dst[i]] = *(const uint4*)&s_wd_lo[b_src[i] + kc];
        }
        __syncthreads();

        #pragma unroll
        for (int ks = 0; ks < 2; ks++) {
            uint32_t kh = ks * 16;
            uint32_t ah[2][4], al[2][4], bh[8][2], bl[8][2];
            #pragma unroll
            for (int mi = 0; mi < 2; mi++) {
                uint32_t base = aL + (wm + 16 * mi) * SA + kh;
                ldsm4(ah[mi], sb + 2 * base);
                ldsm4(al[mi], sb + 2 * (5120 + base));
            }
            #pragma unroll
            for (int ng = 0; ng < 4; ng++) {
                uint32_t base = bL + (wn + 16 * ng) * SA + kh;
                uint32_t t[4];
                ldsm4(t, sb + 2 * (10240 + base));
                bh[2*ng][0] = t[0]; bh[2*ng][1] = t[1]; bh[2*ng+1][0] = t[2]; bh[2*ng+1][1] = t[3];
                ldsm4(t, sb + 2 * (15360 + base));
                bl[2*ng][0] = t[0]; bl[2*ng][1] = t[1]; bl[2*ng+1][0] = t[2]; bl[2*ng+1][1] = t[3];
            }
            #pragma unroll
            for (int mi = 0; mi < 2; mi++)
                #pragma unroll
                for (int ni = 0; ni < 8; ni++) mma_bf16(acc[mi][ni], ah[mi], bh[ni]);
            #pragma unroll
            for (int mi = 0; mi < 2; mi++)
                #pragma unroll
                for (int ni = 0; ni < 8; ni++) mma_bf16(acc[mi][ni], ah[mi], bl[ni]);
            #pragma unroll
            for (int mi = 0; mi < 2; mi++)
                #pragma unroll
                for (int ni = 0; ni < 8; ni++) mma_bf16(acc[mi][ni], al[mi], bh[ni]);
        }
    }

    // epilogue: weighted atomic scatter-add
    int lr = l >> 2, lc = 2 * (l & 3);
    #pragma unroll
    for (int mi = 0; mi < 2; mi++)
        #pragma unroll
        for (int h2 = 0; h2 < 2; h2++) {
            int r = m0 + wm + 16 * mi + lr + 8 * h2;
            if (r < cnt) {
                int tok = g_tok[off + r];
                float wgt = g_wt[off + r];
                float* orow = out + (size_t)tok * T_HIDDEN;
                #pragma unroll
                for (int ni = 0; ni < 8; ni++) {
                    int col = n0 + wn + ni * 8 + lc;
                    atomicAdd(&orow[col],     wgt * acc[mi][ni][2*h2]);
                    atomicAdd(&orow[col + 1], wgt * acc[mi][ni][2*h2+1]);
                }
            }
        }
}

// ================= launch =================
extern "C" void kernel_launch(void* const* d_in, const int* in_sizes, int n_in,
                              void* d_out, int out_size) {
    const float* x   = (const float*)d_in[0];   // [2048, 2048] fp32
    const int*   idx = (const int*)d_in[1];     // [2048, 2] int32/int64 (runtime-detected)
    const float* w   = (const float*)d_in[2];   // [2048, 2] fp32
    const float* Wg  = (const float*)d_in[3];   // [16, 768, 2048] fp32
    const float* Wu  = (const float*)d_in[4];   // [16, 768, 2048] fp32
    const float* Wd  = (const float*)d_in[5];   // [16, 2048, 768] fp32
    float* out = (float*)d_out;                 // [2048, 2048] fp32

    route_kernel<<<1, NTH>>>(idx, w);
    zero_kernel<<<(T_TOKENS * T_HIDDEN / 4) / NTH, NTH>>>((float4*)out);

    int nw4 = (int)(NW / 4);                    // 6,291,456
    conv_kernel<<<nw4 / NTH, NTH>>>((const float4*)Wg, nw4, 0);
    conv_kernel<<<nw4 / NTH, NTH>>>((const float4*)Wu, nw4, 1);
    conv_kernel<<<nw4 / NTH, NTH>>>((const float4*)Wd, nw4, 2);
    int nx4 = T_TOKENS * T_HIDDEN / 4;          // 1,048,576
    conv_kernel<<<nx4 / NTH, NTH>>>((const float4*)x, nx4, 3);

    gemm1_mma<<<dim3(T_INTER / 64, 32, T_NEXP), NTH>>>();
    gemm2_mma<<<dim3(T_HIDDEN / 128, 32, T_NEXP), NTH>>>(out);
}

// round 8
// speedup vs baseline: 2.3018x; 1.1034x over previous
#include <cuda_runtime.h>
#include <cuda_bf16.h>
#include <cstdint>

#define T_TOKENS 2048
#define T_HIDDEN 2048
#define T_INTER  768
#define T_NEXP   16
#define T_NPAIRS 4096
#define NTH 256
#define SA 40          // smem row stride in bf16 elements (80B: conflict-free ldmatrix)

// -------- device-global scratch (no allocations allowed) --------
__device__ int   g_offs[T_NEXP + 1];
__device__ int   g_tok[T_NPAIRS];
__device__ float g_wt[T_NPAIRS];

#define NW ((size_t)T_NEXP * T_INTER * T_HIDDEN)     // 25,165,824 per weight tensor
__device__ alignas(16) __nv_bfloat16 s_x_hi[(size_t)T_TOKENS * T_HIDDEN];
__device__ alignas(16) __nv_bfloat16 s_x_lo[(size_t)T_TOKENS * T_HIDDEN];
__device__ alignas(16) __nv_bfloat16 s_wg_hi[NW];
__device__ alignas(16) __nv_bfloat16 s_wg_lo[NW];
__device__ alignas(16) __nv_bfloat16 s_wu_hi[NW];
__device__ alignas(16) __nv_bfloat16 s_wu_lo[NW];
__device__ alignas(16) __nv_bfloat16 s_wd_hi[NW];
__device__ alignas(16) __nv_bfloat16 s_wd_lo[NW];
__device__ alignas(16) __nv_bfloat16 s_h_hi[(size_t)T_NPAIRS * T_INTER];
__device__ alignas(16) __nv_bfloat16 s_h_lo[(size_t)T_NPAIRS * T_INTER];

// ================= helpers =================
__device__ __forceinline__ uint32_t smem_u32(const void* p) {
    uint32_t a;
    asm("{ .reg .u64 t; cvta.to.shared.u64 t, %1; cvt.u32.u64 %0, t; }" : "=r"(a) : "l"(p));
    return a;
}
__device__ __forceinline__ void pack2(float a, float b, uint32_t& h, uint32_t& l) {
    asm("cvt.rn.bf16x2.f32 %0, %1, %2;" : "=r"(h) : "f"(b), "f"(a));
    float ha = __uint_as_float(h << 16);
    float hb = __uint_as_float(h & 0xffff0000u);
    float la = a - ha;
    float lb = b - hb;
    asm("cvt.rn.bf16x2.f32 %0, %1, %2;" : "=r"(l) : "f"(lb), "f"(la));
}
__device__ __forceinline__ void ldsm4(uint32_t* r, uint32_t addr) {
    asm volatile("ldmatrix.sync.aligned.m8n8.x4.shared.b16 {%0,%1,%2,%3}, [%4];"
                 : "=r"(r[0]), "=r"(r[1]), "=r"(r[2]), "=r"(r[3]) : "r"(addr));
}
__device__ __forceinline__ void mma_bf16(float* d, const uint32_t* a, const uint32_t* b) {
    asm volatile(
        "mma.sync.aligned.m16n8k16.row.col.f32.bf16.bf16.f32 "
        "{%0,%1,%2,%3},{%4,%5,%6,%7},{%8,%9},{%0,%1,%2,%3};"
        : "+f"(d[0]), "+f"(d[1]), "+f"(d[2]), "+f"(d[3])
        : "r"(a[0]), "r"(a[1]), "r"(a[2]), "r"(a[3]), "r"(b[0]), "r"(b[1]));
}
__device__ __forceinline__ void cpa16(uint32_t dst, const void* src) {
    asm volatile("cp.async.ca.shared.global [%0], [%1], 16;" :: "r"(dst), "l"(src) : "memory");
}
#define CP_COMMIT() asm volatile("cp.async.commit_group;" ::: "memory")
#define CP_WAIT1()  asm volatile("cp.async.wait_group 1;"  ::: "memory")
#define CP_WAIT0()  asm volatile("cp.async.wait_group 0;"  ::: "memory")

// ================= routing =================
__global__ void route_kernel(const int* __restrict__ idx32, const float* __restrict__ w) {
    __shared__ int cnt[T_NEXP];
    __shared__ int base[T_NEXP];
    __shared__ int cur[T_NEXP];
    __shared__ int odd_nonzero;
    int tid = threadIdx.x;
    if (tid < T_NEXP) cnt[tid] = 0;
    if (tid == 0) odd_nonzero = 0;
    __syncthreads();
    for (int j = tid; j < T_NPAIRS; j += NTH)
        if ((j & 1) && idx32[j] != 0) odd_nonzero = 1;
    __syncthreads();
    bool i64 = (odd_nonzero == 0);
    for (int p = tid; p < T_NPAIRS; p += NTH) {
        int e = i64 ? idx32[2 * p] : idx32[p];
        atomicAdd(&cnt[e], 1);
    }
    __syncthreads();
    if (tid == 0) {
        int s = 0;
        for (int e = 0; e < T_NEXP; e++) { base[e] = s; cur[e] = 0; g_offs[e] = s; s += cnt[e]; }
        g_offs[T_NEXP] = s;
    }
    __syncthreads();
    for (int p = tid; p < T_NPAIRS; p += NTH) {
        int e = i64 ? idx32[2 * p] : idx32[p];
        int slot = base[e] + atomicAdd(&cur[e], 1);
        g_tok[slot] = p >> 1;
        g_wt[slot]  = w[p];
    }
}

__global__ void zero_kernel(float4* __restrict__ out) {
    out[blockIdx.x * blockDim.x + threadIdx.x] = make_float4(0.f, 0.f, 0.f, 0.f);
}

// ============ fp32 -> bf16 hi/lo conversion (one pass per tensor) ============
__global__ void conv_kernel(const float4* __restrict__ src, int n4, int which) {
    uint2* hi; uint2* lo;
    switch (which) {
        case 0:  hi = (uint2*)s_wg_hi; lo = (uint2*)s_wg_lo; break;
        case 1:  hi = (uint2*)s_wu_hi; lo = (uint2*)s_wu_lo; break;
        case 2:  hi = (uint2*)s_wd_hi; lo = (uint2*)s_wd_lo; break;
        default: hi = (uint2*)s_x_hi;  lo = (uint2*)s_x_lo;  break;
    }
    int i = blockIdx.x * NTH + threadIdx.x;
    if (i >= n4) return;
    float4 v = src[i];
    uint32_t h0, l0, h1, l1;
    pack2(v.x, v.y, h0, l0);
    pack2(v.z, v.w, h1, l1);
    hi[i] = make_uint2(h0, h1);
    lo[i] = make_uint2(l0, l1);
}

// ================= GEMM1: fused gate+up+SwiGLU (mma.sync bf16 hi/lo) =========
// CTA tile M=128 x N=64, K=2048, chunk 32, cp.async double-buffered.
// smem (bf16 el, per buffer): Ah 0, Al 5120, Gh 10240, Gl 12800, Uh 15360, Ul 17920.
#define G1_BUF 20480

__global__ __launch_bounds__(NTH, 2)
void gemm1_mma() {
    int e   = blockIdx.z;
    int off = g_offs[e], cnt = g_offs[e + 1] - off;
    int m0  = blockIdx.y * 128;
    if (m0 >= cnt) return;
    int n0  = blockIdx.x * 64;

    __shared__ alignas(128) __nv_bfloat16 sm[2 * G1_BUF];
    uint32_t sb = smem_u32(sm);
    int tid = threadIdx.x, wid = tid >> 5, l = tid & 31;

    size_t a_src[2]; uint32_t a_dst[2];
    #pragma unroll
    for (int i = 0; i < 2; i++) {
        int q = tid + NTH * i;
        int row = q >> 2, qc = q & 3;
        int r = m0 + row;
        int tok = g_tok[off + (r < cnt ? r : 0)];
        a_src[i] = (size_t)tok * T_HIDDEN + 8 * qc;
        a_dst[i] = row * SA + 8 * qc;
    }
    size_t b_src = (size_t)e * T_INTER * T_HIDDEN
                 + (size_t)(n0 + (tid >> 2)) * T_HIDDEN + 8 * (tid & 3);
    uint32_t b_dst = (tid >> 2) * SA + 8 * (tid & 3);

    int wm = (wid >> 1) * 32, wn = (wid & 1) * 32;
    uint32_t aL = ((l & 7) + ((l >> 3) & 1) * 8) * SA + ((l >> 4) & 1) * 8;
    uint32_t bL = ((l & 7) + ((l >> 4) & 1) * 8) * SA + ((l >> 3) & 1) * 8;

    float accg[2][4][4] = {}, accu[2][4][4] = {};

    // ---- async load of one K-chunk into buffer `bi` ----
    auto load_chunk = [&](int c, int bi) {
        uint32_t st = sb + 2 * (bi * G1_BUF);
        int kc = c * 32;
        #pragma unroll
        for (int i = 0; i < 2; i++) {
            cpa16(st + 2 * a_dst[i],          &s_x_hi[a_src[i] + kc]);
            cpa16(st + 2 * (5120 + a_dst[i]), &s_x_lo[a_src[i] + kc]);
        }
        cpa16(st + 2 * (10240 + b_dst), &s_wg_hi[b_src + kc]);
        cpa16(st + 2 * (12800 + b_dst), &s_wg_lo[b_src + kc]);
        cpa16(st + 2 * (15360 + b_dst), &s_wu_hi[b_src + kc]);
        cpa16(st + 2 * (17920 + b_dst), &s_wu_lo[b_src + kc]);
        CP_COMMIT();
    };

    load_chunk(0, 0);
    const int NC = T_HIDDEN / 32;
    for (int c = 0; c < NC; c++) {
        int buf = c & 1;
        if (c + 1 < NC) { load_chunk(c + 1, buf ^ 1); CP_WAIT1(); }
        else            { CP_WAIT0(); }
        __syncthreads();

        uint32_t s0 = sb + 2 * (buf * G1_BUF);
        #pragma unroll
        for (int ks = 0; ks < 2; ks++) {
            uint32_t kh = ks * 16;
            uint32_t ah[2][4], al[2][4], gh[4][2], gl[4][2], uh[4][2], ul[4][2];
            #pragma unroll
            for (int mi = 0; mi < 2; mi++) {
                uint32_t base = aL + (wm + 16 * mi) * SA + kh;
                ldsm4(ah[mi], s0 + 2 * base);
                ldsm4(al[mi], s0 + 2 * (5120 + base));
            }
            #pragma unroll
            for (int ng = 0; ng < 2; ng++) {
                uint32_t base = bL + (wn + 16 * ng) * SA + kh;
                uint32_t t[4];
                ldsm4(t, s0 + 2 * (10240 + base));
                gh[2*ng][0] = t[0]; gh[2*ng][1] = t[1]; gh[2*ng+1][0] = t[2]; gh[2*ng+1][1] = t[3];
                ldsm4(t, s0 + 2 * (12800 + base));
                gl[2*ng][0] = t[0]; gl[2*ng][1] = t[1]; gl[2*ng+1][0] = t[2]; gl[2*ng+1][1] = t[3];
                ldsm4(t, s0 + 2 * (15360 + base));
                uh[2*ng][0] = t[0]; uh[2*ng][1] = t[1]; uh[2*ng+1][0] = t[2]; uh[2*ng+1][1] = t[3];
                ldsm4(t, s0 + 2 * (17920 + base));
                ul[2*ng][0] = t[0]; ul[2*ng][1] = t[1]; ul[2*ng+1][0] = t[2]; ul[2*ng+1][1] = t[3];
            }
            #pragma unroll
            for (int mi = 0; mi < 2; mi++)
                #pragma unroll
                for (int ni = 0; ni < 4; ni++) mma_bf16(accg[mi][ni], ah[mi], gh[ni]);
            #pragma unroll
            for (int mi = 0; mi < 2; mi++)
                #pragma unroll
                for (int ni = 0; ni < 4; ni++) mma_bf16(accu[mi][ni], ah[mi], uh[ni]);
            #pragma unroll
            for (int mi = 0; mi < 2; mi++)
                #pragma unroll
                for (int ni = 0; ni < 4; ni++) mma_bf16(accg[mi][ni], ah[mi], gl[ni]);
            #pragma unroll
            for (int mi = 0; mi < 2; mi++)
                #pragma unroll
                for (int ni = 0; ni < 4; ni++) mma_bf16(accu[mi][ni], ah[mi], ul[ni]);
            #pragma unroll
            for (int mi = 0; mi < 2; mi++)
                #pragma unroll
                for (int ni = 0; ni < 4; ni++) mma_bf16(accg[mi][ni], al[mi], gh[ni]);
            #pragma unroll
            for (int mi = 0; mi < 2; mi++)
                #pragma unroll
                for (int ni = 0; ni < 4; ni++) mma_bf16(accu[mi][ni], al[mi], uh[ni]);
        }
        __syncthreads();
    }

    // epilogue: silu(g)*u -> bf16 hi/lo planes of h
    int lr = l >> 2, lc = 2 * (l & 3);
    #pragma unroll
    for (int mi = 0; mi < 2; mi++)
        #pragma unroll
        for (int ni = 0; ni < 4; ni++) {
            int col = n0 + wn + ni * 8 + lc;
            #pragma unroll
            for (int h2 = 0; h2 < 2; h2++) {
                int r = m0 + wm + 16 * mi + lr + 8 * h2;
                if (r < cnt) {
                    float g0 = accg[mi][ni][2*h2],     g1 = accg[mi][ni][2*h2+1];
                    float u0 = accu[mi][ni][2*h2],     u1 = accu[mi][ni][2*h2+1];
                    float f0 = g0 / (1.f + __expf(-g0)) * u0;
                    float f1 = g1 / (1.f + __expf(-g1)) * u1;
                    uint32_t hw, lw;
                    pack2(f0, f1, hw, lw);
                    size_t o = (size_t)(off + r) * T_INTER + col;
                    *(uint32_t*)&s_h_hi[o] = hw;
                    *(uint32_t*)&s_h_lo[o] = lw;
                }
            }
        }
}

// ================= GEMM2: down proj + weighted scatter-add ===================
// CTA tile M=128 x N=128, K=768, chunk 32, cp.async double-buffered.
// smem (bf16 el, per buffer): Ah 0, Al 5120, Bh 10240, Bl 15360.
#define G2_BUF 20480

__global__ __launch_bounds__(NTH, 2)
void gemm2_mma(float* __restrict__ out) {
    int e   = blockIdx.z;
    int off = g_offs[e], cnt = g_offs[e + 1] - off;
    int m0  = blockIdx.y * 128;
    if (m0 >= cnt) return;
    int n0  = blockIdx.x * 128;

    __shared__ alignas(128) __nv_bfloat16 sm[2 * G2_BUF];
    uint32_t sb = smem_u32(sm);
    int tid = threadIdx.x, wid = tid >> 5, l = tid & 31;

    size_t a_src[2], b_src[2]; uint32_t ab_dst[2];
    #pragma unroll
    for (int i = 0; i < 2; i++) {
        int q = tid + NTH * i;
        int row = q >> 2, qc = q & 3;
        int sl = off + m0 + row;
        if (sl > T_NPAIRS - 1) sl = T_NPAIRS - 1;
        a_src[i] = (size_t)sl * T_INTER + 8 * qc;
        b_src[i] = (size_t)e * T_HIDDEN * T_INTER + (size_t)(n0 + row) * T_INTER + 8 * qc;
        ab_dst[i] = row * SA + 8 * qc;
    }
    int wm = (wid >> 1) * 32, wn = (wid & 1) * 64;
    uint32_t aL = ((l & 7) + ((l >> 3) & 1) * 8) * SA + ((l >> 4) & 1) * 8;
    uint32_t bL = ((l & 7) + ((l >> 4) & 1) * 8) * SA + ((l >> 3) & 1) * 8;

    float acc[2][8][4] = {};

    auto load_chunk = [&](int c, int bi) {
        uint32_t st = sb + 2 * (bi * G2_BUF);
        int kc = c * 32;
        #pragma unroll
        for (int i = 0; i < 2; i++) {
            cpa16(st + 2 * ab_dst[i],           &s_h_hi[a_src[i] + kc]);
            cpa16(st + 2 * (5120  + ab_dst[i]), &s_h_lo[a_src[i] + kc]);
            cpa16(st + 2 * (10240 + ab_dst[i]), &s_wd_hi[b_src[i] + kc]);
            cpa16(st + 2 * (15360 + ab_dst[i]), &s_wd_lo[b_src[i] + kc]);
        }
        CP_COMMIT();
    };

    load_chunk(0, 0);
    const int NC = T_INTER / 32;
    for (int c = 0; c < NC; c++) {
        int buf = c & 1;
        if (c + 1 < NC) { load_chunk(c + 1, buf ^ 1); CP_WAIT1(); }
        else            { CP_WAIT0(); }
        __syncthreads();

        uint32_t s0 = sb + 2 * (buf * G2_BUF);
        #pragma unroll
        for (int ks = 0; ks < 2; ks++) {
            uint32_t kh = ks * 16;
            uint32_t ah[2][4], al[2][4], bh[8][2], bl[8][2];
            #pragma unroll
            for (int mi = 0; mi < 2; mi++) {
                uint32_t base = aL + (wm + 16 * mi) * SA + kh;
                ldsm4(ah[mi], s0 + 2 * base);
                ldsm4(al[mi], s0 + 2 * (5120 + base));
            }
            #pragma unroll
            for (int ng = 0; ng < 4; ng++) {
                uint32_t base = bL + (wn + 16 * ng) * SA + kh;
                uint32_t t[4];
                ldsm4(t, s0 + 2 * (10240 + base));
                bh[2*ng][0] = t[0]; bh[2*ng][1] = t[1]; bh[2*ng+1][0] = t[2]; bh[2*ng+1][1] = t[3];
                ldsm4(t, s0 + 2 * (15360 + base));
                bl[2*ng][0] = t[0]; bl[2*ng][1] = t[1]; bl[2*ng+1][0] = t[2]; bl[2*ng+1][1] = t[3];
            }
            #pragma unroll
            for (int mi = 0; mi < 2; mi++)
                #pragma unroll
                for (int ni = 0; ni < 8; ni++) mma_bf16(acc[mi][ni], ah[mi], bh[ni]);
            #pragma unroll
            for (int mi = 0; mi < 2; mi++)
                #pragma unroll
                for (int ni = 0; ni < 8; ni++) mma_bf16(acc[mi][ni], ah[mi], bl[ni]);
            #pragma unroll
            for (int mi = 0; mi < 2; mi++)
                #pragma unroll
                for (int ni = 0; ni < 8; ni++) mma_bf16(acc[mi][ni], al[mi], bh[ni]);
        }
        __syncthreads();
    }

    // epilogue: weighted atomic scatter-add
    int lr = l >> 2, lc = 2 * (l & 3);
    #pragma unroll
    for (int mi = 0; mi < 2; mi++)
        #pragma unroll
        for (int h2 = 0; h2 < 2; h2++) {
            int r = m0 + wm + 16 * mi + lr + 8 * h2;
            if (r < cnt) {
                int tok = g_tok[off + r];
                float wgt = g_wt[off + r];
                float* orow = out + (size_t)tok * T_HIDDEN;
                #pragma unroll
                for (int ni = 0; ni < 8; ni++) {
                    int col = n0 + wn + ni * 8 + lc;
                    atomicAdd(&orow[col],     wgt * acc[mi][ni][2*h2]);
                    atomicAdd(&orow[col + 1], wgt * acc[mi][ni][2*h2+1]);
                }
            }
        }
}

// ================= launch =================
extern "C" void kernel_launch(void* const* d_in, const int* in_sizes, int n_in,
                              void* d_out, int out_size) {
    const float* x   = (const float*)d_in[0];   // [2048, 2048] fp32
    const int*   idx = (const int*)d_in[1];     // [2048, 2] int32/int64 (runtime-detected)
    const float* w   = (const float*)d_in[2];   // [2048, 2] fp32
    const float* Wg  = (const float*)d_in[3];   // [16, 768, 2048] fp32
    const float* Wu  = (const float*)d_in[4];   // [16, 768, 2048] fp32
    const float* Wd  = (const float*)d_in[5];   // [16, 2048, 768] fp32
    float* out = (float*)d_out;                 // [2048, 2048] fp32

    route_kernel<<<1, NTH>>>(idx, w);
    zero_kernel<<<(T_TOKENS * T_HIDDEN / 4) / NTH, NTH>>>((float4*)out);

    int nw4 = (int)(NW / 4);                    // 6,291,456
    int nx4 = T_TOKENS * T_HIDDEN / 4;          // 1,048,576
    conv_kernel<<<nx4 / NTH, NTH>>>((const float4*)x, nx4, 3);
    conv_kernel<<<nw4 / NTH, NTH>>>((const float4*)Wg, nw4, 0);
    conv_kernel<<<nw4 / NTH, NTH>>>((const float4*)Wu, nw4, 1);

    gemm1_mma<<<dim3(T_INTER / 64, 32, T_NEXP), NTH>>>();

    conv_kernel<<<nw4 / NTH, NTH>>>((const float4*)Wd, nw4, 2);
    gemm2_mma<<<dim3(T_HIDDEN / 128, 32, T_NEXP), NTH>>>(out);
}